// round 1
// baseline (speedup 1.0000x reference)
#include <cuda_runtime.h>
#include <cuda_bf16.h>
#include <cstdint>

namespace {

constexpr int S = 8192;          // sequence length per batch row
constexpr int T = 32768;         // 4 * 8192 tokens
constexpr int H = 64;            // hash dim (K of GEMM)
constexpr int MOUT = 1024;       // model dim (N of GEMM)
constexpr long long HASH_MULT = 92821;
constexpr long long NUM_BUCKETS = 2000003;

constexpr int BM = 128;          // tokens per block
constexpr int BN = 128;          // output cols per inner iteration
constexpr int AST = H + 8;       // padded smem row stride (72 bf16 = 144 B)

// 1 if input_ids buffer is int64-laid-out, 0 if int32.
__device__ int g_ids64;

// Detect int64 vs int32 token buffer: token ids are in [0, 50257), so if the
// buffer is int64 every odd 32-bit word is zero. If it is int32, the odd words
// are real token ids (16384 random samples -> all-zero is impossible).
__global__ void detect_ids_kernel(const int* __restrict__ ids32) {
    __shared__ int any_nonzero;
    if (threadIdx.x == 0) any_nonzero = 0;
    __syncthreads();
    int local = 0;
    // only scan the first half of tokens: index 2*i+1 stays within a 32768-elem
    // int32 buffer (i < 16384 -> max index 32767)
    for (int i = threadIdx.x; i < T / 2; i += blockDim.x)
        local |= ids32[2 * i + 1];
    if (local) atomicOr(&any_nonzero, 1);
    __syncthreads();
    if (threadIdx.x == 0) g_ids64 = (any_nonzero == 0) ? 1 : 0;
}

__device__ __forceinline__ void ldmatrix_x4(uint32_t r[4], uint32_t addr) {
    asm volatile(
        "ldmatrix.sync.aligned.m8n8.x4.shared.b16 {%0,%1,%2,%3}, [%4];"
        : "=r"(r[0]), "=r"(r[1]), "=r"(r[2]), "=r"(r[3])
        : "r"(addr));
}

__device__ __forceinline__ void mma_bf16(float c[4], const uint32_t a[4],
                                         uint32_t b0, uint32_t b1) {
    asm volatile(
        "mma.sync.aligned.m16n8k16.row.col.f32.bf16.bf16.f32 "
        "{%0,%1,%2,%3}, {%4,%5,%6,%7}, {%8,%9}, {%0,%1,%2,%3};"
        : "+f"(c[0]), "+f"(c[1]), "+f"(c[2]), "+f"(c[3])
        : "r"(a[0]), "r"(a[1]), "r"(a[2]), "r"(a[3]), "r"(b0), "r"(b1));
}

__global__ __launch_bounds__(256, 1)
void bigram_kernel(const int* __restrict__ ids, const float* __restrict__ table,
                   const float* __restrict__ proj, float* __restrict__ out) {
    __shared__ __nv_bfloat16 As[BM][AST];   // emb tile (tokens x K), bf16
    __shared__ __nv_bfloat16 Ws[BN][AST];   // W tile   (N x K), bf16

    const int tid = threadIdx.x;
    const int warp = tid >> 5;
    const int lane = tid & 31;
    const int wm = warp >> 1;   // 0..3 : M position (32 rows each)
    const int wn = warp & 1;    // 0..1 : N position (64 cols each)
    const int t0 = blockIdx.x * BM;
    const int id_stride = g_ids64 ? 2 : 1;

    // ---- Hash + gather embedding tile (once per block) ----
    {
        const int tl = tid >> 1;           // local token 0..127
        const int half = tid & 1;          // which 32-float half of the row
        const int t = t0 + tl;
        long long cur = ids[(long long)t * id_stride];
        long long prev = ((t & (S - 1)) == 0)
                             ? 0
                             : (long long)ids[(long long)(t - 1) * id_stride];
        long long h = (prev * HASH_MULT + cur) % NUM_BUCKETS;
        const float4* src =
            reinterpret_cast<const float4*>(table + h * H + half * 32);
        __nv_bfloat162* dst =
            reinterpret_cast<__nv_bfloat162*>(&As[tl][half * 32]);
#pragma unroll
        for (int i = 0; i < 8; i++) {
            float4 v = src[i];
            dst[2 * i]     = __floats2bfloat162_rn(v.x, v.y);
            dst[2 * i + 1] = __floats2bfloat162_rn(v.z, v.w);
        }
    }
    __syncthreads();

    // ---- Load A fragments once; reused across all 8 N-tiles ----
    uint32_t afrag[2][4][4];  // [m-subtile][k-step][reg]
#pragma unroll
    for (int mi = 0; mi < 2; mi++) {
#pragma unroll
        for (int ks = 0; ks < 4; ks++) {
            const int row = wm * 32 + mi * 16 + (lane & 15);
            const int col = ks * 16 + ((lane >> 4) << 3);
            uint32_t addr = (uint32_t)__cvta_generic_to_shared(&As[row][col]);
            ldmatrix_x4(afrag[mi][ks], addr);
        }
    }

    const int b_row = wn * 64 + (lane >> 2);
    const int b_col = (lane & 3) * 2;

    for (int nt = 0; nt < MOUT / BN; nt++) {
        __syncthreads();  // prior iteration's Ws reads complete before overwrite

        // ---- Stage W tile (fp32 -> bf16) ----
        {
            const int r = tid >> 1;
            const int half = tid & 1;
            const int n = nt * BN + r;
            const float4* src =
                reinterpret_cast<const float4*>(proj + n * H + half * 32);
            __nv_bfloat162* dst =
                reinterpret_cast<__nv_bfloat162*>(&Ws[r][half * 32]);
#pragma unroll
            for (int i = 0; i < 8; i++) {
                float4 v = src[i];
                dst[2 * i]     = __floats2bfloat162_rn(v.x, v.y);
                dst[2 * i + 1] = __floats2bfloat162_rn(v.z, v.w);
            }
        }
        __syncthreads();

        // ---- MMA: warp computes 32 x 64 of this 128-col tile ----
        float c[2][8][4];
#pragma unroll
        for (int mi = 0; mi < 2; mi++)
#pragma unroll
            for (int ni = 0; ni < 8; ni++)
#pragma unroll
                for (int r = 0; r < 4; r++) c[mi][ni][r] = 0.0f;

#pragma unroll
        for (int ks = 0; ks < 4; ks++) {
#pragma unroll
            for (int ni = 0; ni < 8; ni++) {
                uint32_t b0 = *reinterpret_cast<const uint32_t*>(
                    &Ws[b_row + ni * 8][ks * 16 + b_col]);
                uint32_t b1 = *reinterpret_cast<const uint32_t*>(
                    &Ws[b_row + ni * 8][ks * 16 + b_col + 8]);
                mma_bf16(c[0][ni], afrag[0][ks], b0, b1);
                mma_bf16(c[1][ni], afrag[1][ks], b0, b1);
            }
        }

        // ---- Epilogue: direct f32 stores ----
        const int col_base = nt * BN + wn * 64 + (lane & 3) * 2;
#pragma unroll
        for (int mi = 0; mi < 2; mi++) {
            const int row = t0 + wm * 32 + mi * 16 + (lane >> 2);
#pragma unroll
            for (int ni = 0; ni < 8; ni++) {
                const int col = col_base + ni * 8;
                float2* p0 = reinterpret_cast<float2*>(
                    &out[(long long)row * MOUT + col]);
                float2* p1 = reinterpret_cast<float2*>(
                    &out[(long long)(row + 8) * MOUT + col]);
                *p0 = make_float2(c[mi][ni][0], c[mi][ni][1]);
                *p1 = make_float2(c[mi][ni][2], c[mi][ni][3]);
            }
        }
    }
}

}  // namespace

extern "C" void kernel_launch(void* const* d_in, const int* in_sizes, int n_in,
                              void* d_out, int out_size) {
    // Map inputs by element count (robust to ordering):
    //   ids:   32768, table: 2000003*64 = 128000192, proj: 1024*64 = 65536
    const int* ids = nullptr;
    const float* table = nullptr;
    const float* proj = nullptr;
    for (int i = 0; i < n_in; i++) {
        if (in_sizes[i] == T) ids = (const int*)d_in[i];
        else if (in_sizes[i] == (int)(NUM_BUCKETS * H)) table = (const float*)d_in[i];
        else if (in_sizes[i] == MOUT * H) proj = (const float*)d_in[i];
    }

    detect_ids_kernel<<<1, 256>>>(ids);
    bigram_kernel<<<T / BM, 256>>>(ids, table, proj, (float*)d_out);
}

// round 3
// speedup vs baseline: 1.3090x; 1.3090x over previous
#include <cuda_runtime.h>
#include <cuda_bf16.h>
#include <cstdint>

namespace {

constexpr int S = 8192;          // sequence length per batch row
constexpr int T = 32768;         // 4 * 8192 tokens
constexpr int H = 64;            // hash dim (K of GEMM)
constexpr int MOUT = 1024;       // model dim (N of GEMM)
constexpr long long HASH_MULT = 92821;
constexpr long long NUM_BUCKETS = 2000003;

constexpr int BM = 64;           // tokens per block
constexpr int BN = 64;           // output cols per inner iteration
constexpr int NT = MOUT / BN;    // 16 N-tiles
constexpr int AST = H + 8;       // padded smem row stride (72 bf16 = 144 B)

// 1 if input_ids buffer is int64-laid-out, 0 if int32.
__device__ int g_ids64;
// proj_w pre-converted to bf16, row-major [MOUT][H]
__device__ __nv_bfloat16 g_wbf16[MOUT * H];

__global__ void detect_ids_kernel(const int* __restrict__ ids32) {
    __shared__ int any_nonzero;
    if (threadIdx.x == 0) any_nonzero = 0;
    __syncthreads();
    int local = 0;
    for (int i = threadIdx.x; i < T / 2; i += blockDim.x)
        local |= ids32[2 * i + 1];  // stays in-bounds for the int32 layout
    if (local) atomicOr(&any_nonzero, 1);
    __syncthreads();
    if (threadIdx.x == 0) g_ids64 = (any_nonzero == 0) ? 1 : 0;
}

// Convert proj_w (f32) -> g_wbf16 once per launch. 65536 elems, 8 per thread.
__global__ void convert_w_kernel(const float* __restrict__ proj) {
    int base = (blockIdx.x * blockDim.x + threadIdx.x) * 8;
    float4 v0 = *reinterpret_cast<const float4*>(proj + base);
    float4 v1 = *reinterpret_cast<const float4*>(proj + base + 4);
    __nv_bfloat162 b[4];
    b[0] = __floats2bfloat162_rn(v0.x, v0.y);
    b[1] = __floats2bfloat162_rn(v0.z, v0.w);
    b[2] = __floats2bfloat162_rn(v1.x, v1.y);
    b[3] = __floats2bfloat162_rn(v1.z, v1.w);
    *reinterpret_cast<uint4*>(g_wbf16 + base) = *reinterpret_cast<uint4*>(b);
}

__device__ __forceinline__ void ldmatrix_x4(uint32_t r[4], uint32_t addr) {
    asm volatile(
        "ldmatrix.sync.aligned.m8n8.x4.shared.b16 {%0,%1,%2,%3}, [%4];"
        : "=r"(r[0]), "=r"(r[1]), "=r"(r[2]), "=r"(r[3])
        : "r"(addr));
}

__device__ __forceinline__ void mma_bf16(float c[4], const uint32_t a[4],
                                         uint32_t b0, uint32_t b1) {
    asm volatile(
        "mma.sync.aligned.m16n8k16.row.col.f32.bf16.bf16.f32 "
        "{%0,%1,%2,%3}, {%4,%5,%6,%7}, {%8,%9}, {%0,%1,%2,%3};"
        : "+f"(c[0]), "+f"(c[1]), "+f"(c[2]), "+f"(c[3])
        : "r"(a[0]), "r"(a[1]), "r"(a[2]), "r"(a[3]), "r"(b0), "r"(b1));
}

__global__ __launch_bounds__(256, 4)
void bigram_kernel(const int* __restrict__ ids, const float* __restrict__ table,
                   float* __restrict__ out) {
    __shared__ __align__(16) __nv_bfloat16 As[BM][AST];    // emb tile (M x K)
    __shared__ __align__(16) __nv_bfloat16 Ws[2][BN][AST]; // ping-pong W (N x K)

    const int tid = threadIdx.x;
    const int warp = tid >> 5;
    const int lane = tid & 31;
    const int wm = warp >> 1;   // 0..3 : M position (16 rows each)
    const int wn = warp & 1;    // 0..1 : N position (32 cols each)
    const int t0 = blockIdx.x * BM;
    const int id_stride = g_ids64 ? 2 : 1;

    // ---- Hash + gather embedding tile (once per block) ----
    {
        const int tl = tid >> 2;           // local token 0..63
        const int q = tid & 3;             // 16-float quarter of the row
        const int t = t0 + tl;
        long long cur = ids[(long long)t * id_stride];
        long long prev = ((t & (S - 1)) == 0)
                             ? 0
                             : (long long)ids[(long long)(t - 1) * id_stride];
        long long h = (prev * HASH_MULT + cur) % NUM_BUCKETS;
        const float4* src =
            reinterpret_cast<const float4*>(table + h * H + q * 16);
        __nv_bfloat162* dst = reinterpret_cast<__nv_bfloat162*>(&As[tl][q * 16]);
#pragma unroll
        for (int i = 0; i < 4; i++) {
            float4 v = src[i];
            dst[2 * i]     = __floats2bfloat162_rn(v.x, v.y);
            dst[2 * i + 1] = __floats2bfloat162_rn(v.z, v.w);
        }
    }
    __syncthreads();

    // ---- Load A fragments once; reused across all 16 N-tiles ----
    uint32_t afrag[4][4];  // [k-step][reg]
#pragma unroll
    for (int ks = 0; ks < 4; ks++) {
        const int row = wm * 16 + (lane & 15);
        const int col = ks * 16 + ((lane >> 4) << 3);
        uint32_t addr = (uint32_t)__cvta_generic_to_shared(&As[row][col]);
        ldmatrix_x4(afrag[ks], addr);
    }

    const int b_row = wn * 32 + (lane >> 2);
    const int b_col = (lane & 3) * 2;

    for (int nt = 0; nt < NT; nt++) {
        const int buf = nt & 1;
        // ---- Stage W tile: 64x64 bf16 = 512 uint4; 2 uint4 per thread ----
        {
#pragma unroll
            for (int rep = 0; rep < 2; rep++) {
                const int j = tid + rep * 256;   // uint4 index 0..511
                const int r = j >> 3;            // row 0..63
                const int cp = (j & 7) * 8;      // col 0,8,...,56 (8 bf16 chunks)
                const uint4 v = *reinterpret_cast<const uint4*>(
                    g_wbf16 + (nt * BN + r) * H + cp);
                *reinterpret_cast<uint4*>(&Ws[buf][r][cp]) = v;
            }
        }
        __syncthreads();

        // ---- MMA: warp computes 16 x 32 of this 64-col tile ----
        float c[4][4];
#pragma unroll
        for (int ni = 0; ni < 4; ni++)
#pragma unroll
            for (int r = 0; r < 4; r++) c[ni][r] = 0.0f;

#pragma unroll
        for (int ks = 0; ks < 4; ks++) {
#pragma unroll
            for (int ni = 0; ni < 4; ni++) {
                uint32_t b0 = *reinterpret_cast<const uint32_t*>(
                    &Ws[buf][b_row + ni * 8][ks * 16 + b_col]);
                uint32_t b1 = *reinterpret_cast<const uint32_t*>(
                    &Ws[buf][b_row + ni * 8][ks * 16 + b_col + 8]);
                mma_bf16(c[ni], afrag[ks], b0, b1);
            }
        }

        // ---- Epilogue: direct f32 stores ----
        const int row = t0 + wm * 16 + (lane >> 2);
        const int col_base = nt * BN + wn * 32 + (lane & 3) * 2;
#pragma unroll
        for (int ni = 0; ni < 4; ni++) {
            const int col = col_base + ni * 8;
            *reinterpret_cast<float2*>(&out[(long long)row * MOUT + col]) =
                make_float2(c[ni][0], c[ni][1]);
            *reinterpret_cast<float2*>(&out[(long long)(row + 8) * MOUT + col]) =
                make_float2(c[ni][2], c[ni][3]);
        }
    }
}

}  // namespace

extern "C" void kernel_launch(void* const* d_in, const int* in_sizes, int n_in,
                              void* d_out, int out_size) {
    const int* ids = nullptr;
    const float* table = nullptr;
    const float* proj = nullptr;
    for (int i = 0; i < n_in; i++) {
        if (in_sizes[i] == T) ids = (const int*)d_in[i];
        else if (in_sizes[i] == (int)(NUM_BUCKETS * H)) table = (const float*)d_in[i];
        else if (in_sizes[i] == MOUT * H) proj = (const float*)d_in[i];
    }

    detect_ids_kernel<<<1, 256>>>(ids);
    convert_w_kernel<<<MOUT * H / (256 * 8), 256>>>(proj);
    bigram_kernel<<<T / BM, 256>>>(ids, table, (float*)d_out);
}

// round 4
// speedup vs baseline: 1.5336x; 1.1715x over previous
#include <cuda_runtime.h>
#include <cuda_bf16.h>
#include <cstdint>

namespace {

constexpr int S = 8192;          // sequence length per batch row
constexpr int T = 32768;         // 4 * 8192 tokens
constexpr int H = 64;            // hash dim (K of GEMM)
constexpr int MOUT = 1024;       // model dim (N of GEMM)
constexpr long long HASH_MULT = 92821;
constexpr long long NUM_BUCKETS = 2000003;

constexpr int BM = 64;           // tokens per block
constexpr int BN = 64;           // output cols per inner iteration
constexpr int NT = MOUT / BN;    // 16 N-tiles
constexpr int AST = H + 8;       // padded smem row stride (72 bf16 = 144 B)

// proj_w pre-converted to bf16, row-major [MOUT][H]
__device__ __nv_bfloat16 g_wbf16[MOUT * H];

// Convert proj_w (f32) -> g_wbf16 once per launch. 65536 elems, 8 per thread.
__global__ void convert_w_kernel(const float* __restrict__ proj) {
    int base = (blockIdx.x * blockDim.x + threadIdx.x) * 8;
    float4 v0 = *reinterpret_cast<const float4*>(proj + base);
    float4 v1 = *reinterpret_cast<const float4*>(proj + base + 4);
    __nv_bfloat162 b[4];
    b[0] = __floats2bfloat162_rn(v0.x, v0.y);
    b[1] = __floats2bfloat162_rn(v0.z, v0.w);
    b[2] = __floats2bfloat162_rn(v1.x, v1.y);
    b[3] = __floats2bfloat162_rn(v1.z, v1.w);
    *reinterpret_cast<uint4*>(g_wbf16 + base) = *reinterpret_cast<uint4*>(b);
}

__device__ __forceinline__ void ldmatrix_x4(uint32_t r[4], uint32_t addr) {
    asm volatile(
        "ldmatrix.sync.aligned.m8n8.x4.shared.b16 {%0,%1,%2,%3}, [%4];"
        : "=r"(r[0]), "=r"(r[1]), "=r"(r[2]), "=r"(r[3])
        : "r"(addr));
}

__device__ __forceinline__ void mma_bf16(float c[4], const uint32_t a[4],
                                         uint32_t b0, uint32_t b1) {
    asm volatile(
        "mma.sync.aligned.m16n8k16.row.col.f32.bf16.bf16.f32 "
        "{%0,%1,%2,%3}, {%4,%5,%6,%7}, {%8,%9}, {%0,%1,%2,%3};"
        : "+f"(c[0]), "+f"(c[1]), "+f"(c[2]), "+f"(c[3])
        : "r"(a[0]), "r"(a[1]), "r"(a[2]), "r"(a[3]), "r"(b0), "r"(b1));
}

__global__ __launch_bounds__(256, 4)
void bigram_kernel(const int* __restrict__ ids, const float* __restrict__ table,
                   float* __restrict__ out) {
    __shared__ __align__(16) __nv_bfloat16 As[BM][AST];    // emb tile (M x K)
    __shared__ __align__(16) __nv_bfloat16 Ws[2][BN][AST]; // ping-pong W (N x K)

    const int tid = threadIdx.x;
    const int warp = tid >> 5;
    const int lane = tid & 31;
    const int wm = warp >> 1;   // 0..3 : M position (16 rows each)
    const int wn = warp & 1;    // 0..1 : N position (32 cols each)
    const int t0 = blockIdx.x * BM;

    // ---- Local layout detection (no extra kernel) ----
    // Odd words at indices 1..127 are in-bounds for both layouts. All-zero
    // <=> int64 layout (token values are < 2^31 and nonnegative). For int32
    // layout these words are token ids; 64 simultaneous zeros cannot happen.
    const int probe = ids[2 * (tid & 63) + 1];
    const int id_stride = __syncthreads_or(probe) ? 1 : 2;

    // ---- Hash + gather embedding tile (once per block) ----
    {
        const int tl = tid >> 2;           // local token 0..63
        const int q = tid & 3;             // 16-float quarter of the row
        const int t = t0 + tl;
        long long cur = ids[(long long)t * id_stride];
        long long prev = ((t & (S - 1)) == 0)
                             ? 0
                             : (long long)ids[(long long)(t - 1) * id_stride];
        long long h = (prev * HASH_MULT + cur) % NUM_BUCKETS;
        const float4* src =
            reinterpret_cast<const float4*>(table + h * H + q * 16);
        __nv_bfloat162* dst = reinterpret_cast<__nv_bfloat162*>(&As[tl][q * 16]);
#pragma unroll
        for (int i = 0; i < 4; i++) {
            float4 v = src[i];
            dst[2 * i]     = __floats2bfloat162_rn(v.x, v.y);
            dst[2 * i + 1] = __floats2bfloat162_rn(v.z, v.w);
        }
    }

    // ---- Prefetch W tile 0 into registers (overlaps with gather) ----
    // Each thread moves 2 uint4 = 32 B of the 8 KB tile.
    const int j0 = tid;                 // uint4 index 0..255
    const int j1 = tid + 256;           // uint4 index 256..511
    const int r0 = j0 >> 3, c0 = (j0 & 7) * 8;
    const int r1 = j1 >> 3, c1 = (j1 & 7) * 8;
    uint4 w0 = *reinterpret_cast<const uint4*>(g_wbf16 + r0 * H + c0);
    uint4 w1 = *reinterpret_cast<const uint4*>(g_wbf16 + r1 * H + c1);

    __syncthreads();  // As tile complete

    // ---- Load A fragments once; reused across all 16 N-tiles ----
    uint32_t afrag[4][4];  // [k-step][reg]
#pragma unroll
    for (int ks = 0; ks < 4; ks++) {
        const int row = wm * 16 + (lane & 15);
        const int col = ks * 16 + ((lane >> 4) << 3);
        uint32_t addr = (uint32_t)__cvta_generic_to_shared(&As[row][col]);
        ldmatrix_x4(afrag[ks], addr);
    }

    const int b_row = wn * 32 + (lane >> 2);
    const int b_col = (lane & 3) * 2;

    for (int nt = 0; nt < NT; nt++) {
        const int buf = nt & 1;
        // ---- Commit prefetched W tile to smem ----
        *reinterpret_cast<uint4*>(&Ws[buf][r0][c0]) = w0;
        *reinterpret_cast<uint4*>(&Ws[buf][r1][c1]) = w1;
        __syncthreads();

        // ---- Issue next tile's loads early (latency hidden by MMA) ----
        if (nt + 1 < NT) {
            w0 = *reinterpret_cast<const uint4*>(
                g_wbf16 + ((nt + 1) * BN + r0) * H + c0);
            w1 = *reinterpret_cast<const uint4*>(
                g_wbf16 + ((nt + 1) * BN + r1) * H + c1);
        }

        // ---- MMA: warp computes 16 x 32 of this 64-col tile ----
        float c[4][4];
#pragma unroll
        for (int ni = 0; ni < 4; ni++)
#pragma unroll
            for (int r = 0; r < 4; r++) c[ni][r] = 0.0f;

#pragma unroll
        for (int ks = 0; ks < 4; ks++) {
#pragma unroll
            for (int ni = 0; ni < 4; ni++) {
                uint32_t b0 = *reinterpret_cast<const uint32_t*>(
                    &Ws[buf][b_row + ni * 8][ks * 16 + b_col]);
                uint32_t b1 = *reinterpret_cast<const uint32_t*>(
                    &Ws[buf][b_row + ni * 8][ks * 16 + b_col + 8]);
                mma_bf16(c[ni], afrag[ks], b0, b1);
            }
        }

        // ---- Epilogue: direct f32 stores ----
        const int row = t0 + wm * 16 + (lane >> 2);
        const int col_base = nt * BN + wn * 32 + (lane & 3) * 2;
#pragma unroll
        for (int ni = 0; ni < 4; ni++) {
            const int col = col_base + ni * 8;
            *reinterpret_cast<float2*>(&out[(long long)row * MOUT + col]) =
                make_float2(c[ni][0], c[ni][1]);
            *reinterpret_cast<float2*>(&out[(long long)(row + 8) * MOUT + col]) =
                make_float2(c[ni][2], c[ni][3]);
        }
    }
}

}  // namespace

extern "C" void kernel_launch(void* const* d_in, const int* in_sizes, int n_in,
                              void* d_out, int out_size) {
    const int* ids = nullptr;
    const float* table = nullptr;
    const float* proj = nullptr;
    for (int i = 0; i < n_in; i++) {
        if (in_sizes[i] == T) ids = (const int*)d_in[i];
        else if (in_sizes[i] == (int)(NUM_BUCKETS * H)) table = (const float*)d_in[i];
        else if (in_sizes[i] == MOUT * H) proj = (const float*)d_in[i];
    }

    convert_w_kernel<<<MOUT * H / (256 * 8), 256>>>(proj);
    bigram_kernel<<<T / BM, 256>>>(ids, table, (float*)d_out);
}